// round 14
// baseline (speedup 1.0000x reference)
#include <cuda_runtime.h>
#include <cuda_bf16.h>
#include <math.h>
#include <stdint.h>

#define Bc 16
#define Lc 128
#define Dc 8
#define Hc 128
#define NLc 2

// bf16 tile geometry: [128 rows][136 cols] bf16, pitch 272B
#define WPITCH 136
#define TILE_ELEMS (128*WPITCH)          // 17408
#define TILE_BYTES (TILE_ELEMS*2)        // 34816

// ---------------- scratch (static device globals; no allocation) ----------------
__device__ __align__(16) float g_ts[Bc*Lc];
__device__ __align__(16) float g_h[Bc*Lc*Hc];
__device__ __align__(16) float g_sa[Bc*Lc*Hc];
__device__ __align__(16) float g_da[Bc*Lc*Hc];
__device__ __align__(16) float g_sm[Bc*Lc*Hc];
__device__ __align__(16) float g_aggpre[Bc*Lc*Hc];
__device__ __align__(16) float g_ba[NLc*Hc];
__device__ __align__(16) float g_bm[NLc*Hc];
__device__ __align__(16) float g_Wco[NLc*Hc*Hc];   // Wm2 @ Wo1a folded
__device__ __align__(16) float g_bco[NLc*Hc];      // bm2 @ Wo1a + bo1
// folded weights as bf16, [k][c] rows padded to 136: per layer Wa | Wm
__device__ __align__(16) __nv_bfloat16 g_Wbf[NLc*2*TILE_ELEMS];

// ---------------- helpers ----------------
__device__ __forceinline__ uint32_t smem_u32(const void* p){
    uint32_t a;
    asm("{ .reg .u64 t; cvta.to.shared.u64 t, %1; cvt.u32.u64 %0, t; }" : "=r"(a) : "l"(p));
    return a;
}
__device__ __forceinline__ void cp16(void* dst_smem, const void* src){
    unsigned sdst = (unsigned)__cvta_generic_to_shared(dst_smem);
    asm volatile("cp.async.cg.shared.global [%0], [%1], 16;" :: "r"(sdst), "l"(src));
}
__device__ __forceinline__ float tanh_fast(float x){
    float r; asm("tanh.approx.f32 %0, %1;" : "=f"(r) : "f"(x)); return r;
}
__device__ __forceinline__ void ldsm4(uint32_t &r0,uint32_t &r1,uint32_t &r2,uint32_t &r3,uint32_t a){
    asm volatile("ldmatrix.sync.aligned.m8n8.x4.shared.b16 {%0,%1,%2,%3},[%4];"
        : "=r"(r0),"=r"(r1),"=r"(r2),"=r"(r3) : "r"(a));
}
__device__ __forceinline__ void ldsm4t(uint32_t &r0,uint32_t &r1,uint32_t &r2,uint32_t &r3,uint32_t a){
    asm volatile("ldmatrix.sync.aligned.m8n8.x4.trans.shared.b16 {%0,%1,%2,%3},[%4];"
        : "=r"(r0),"=r"(r1),"=r"(r2),"=r"(r3) : "r"(a));
}
__device__ __forceinline__ void mma16816(float* d, uint32_t a0,uint32_t a1,uint32_t a2,uint32_t a3,
                                         uint32_t b0,uint32_t b1){
    asm volatile("mma.sync.aligned.m16n8k16.row.col.f32.bf16.bf16.f32 "
        "{%0,%1,%2,%3},{%4,%5,%6,%7},{%8,%9},{%0,%1,%2,%3};"
        : "+f"(d[0]),"+f"(d[1]),"+f"(d[2]),"+f"(d[3])
        : "r"(a0),"r"(a1),"r"(a2),"r"(a3),"r"(b0),"r"(b1));
}
// pack two floats to bf16x2 (v0 -> low half, v1 -> high)
__device__ __forceinline__ uint32_t packbf2(float v0, float v1){
    uint32_t r; asm("cvt.rn.bf16x2.f32 %0, %1, %2;" : "=r"(r) : "f"(v1), "f"(v0)); return r;
}
// packed f32x2 helpers (IEEE fp32 pairwise FMA)
__device__ __forceinline__ void fma2(unsigned long long &acc, unsigned long long a, unsigned long long b){
    asm("fma.rn.f32x2 %0, %1, %2, %0;" : "+l"(acc) : "l"(a), "l"(b));
}
__device__ __forceinline__ unsigned long long pack2(float lo, float hi){
    unsigned long long r; asm("mov.b64 %0, {%1,%2};" : "=l"(r) : "f"(lo), "f"(hi)); return r;
}
__device__ __forceinline__ void unpack2(unsigned long long v, float &lo, float &hi){
    asm("mov.b64 {%0,%1}, %2;" : "=f"(lo), "=f"(hi) : "l"(v));
}

// ---------------- parallel cumsum of ts ----------------
__global__ __launch_bounds__(128)
void k_ts2(const float* __restrict__ hist){
    int b = blockIdx.x;
    int t = threadIdx.x;
    int lane = t & 31, w = t >> 5;
    __shared__ float wsum[4];
    float v = fmaxf(hist[(b*Lc + t)*Dc + 5], 0.f);
    float s = v;
    #pragma unroll
    for(int d = 1; d < 32; d <<= 1){
        float o = __shfl_up_sync(0xffffffffu, s, d);
        if(lane >= d) s += o;
    }
    if(lane == 31) wsum[w] = s;
    __syncthreads();
    float pre = 0.f;
    #pragma unroll
    for(int q = 0; q < 4; q++) pre += (q < w) ? wsum[q] : 0.f;
    g_ts[b*Lc + t] = s + pre;
}

// ---------------- folded weights -> bf16 tiles + Wco/bco fold ----------------
__global__ void k_prepwb(const float* __restrict__ We2, const float* __restrict__ be2,
                         const float* __restrict__ Wa1, const float* __restrict__ Wm1,
                         const float* __restrict__ ba1, const float* __restrict__ bm1,
                         const float* __restrict__ Wm2, const float* __restrict__ bm2,
                         const float* __restrict__ Wo1, const float* __restrict__ bo1){
    int l = blockIdx.x / 129, kk = blockIdx.x % 129;
    int c = threadIdx.x;
    __shared__ float ws[Hc], ws2[Hc];
    if(kk < Hc){
        ws[c]  = We2[l*Hc*Hc + kk*Hc + c];
        ws2[c] = Wm2[l*Hc*Hc + kk*Hc + c];
    } else {
        ws[c]  = be2[l*Hc + c];
        ws2[c] = bm2[l*Hc + c];
    }
    __syncthreads();
    const float* wa  = Wa1 + l*3*Hc*Hc + 2*Hc*Hc;
    const float* wm  = Wm1 + l*2*Hc*Hc + Hc*Hc;
    const float* wo1a = Wo1 + l*2*Hc*Hc + Hc*Hc;
    float sa = 0.f, sm = 0.f, sco = 0.f;
    #pragma unroll 4
    for(int r = 0; r < Hc; r++){
        float w = ws[r], w2 = ws2[r];
        sa += w*wa[r*Hc + c]; sm += w*wm[r*Hc + c]; sco += w2*wo1a[r*Hc + c];
    }
    if(kk < Hc){
        __nv_bfloat16* base = g_Wbf + (size_t)l*2*TILE_ELEMS;
        base[             kk*WPITCH + c] = __float2bfloat16(sa);
        base[TILE_ELEMS + kk*WPITCH + c] = __float2bfloat16(sm);
        g_Wco[(l*Hc + kk)*Hc + c] = sco;
    } else {
        g_ba[l*Hc + c] = sa + ba1[l*Hc + c];
        g_bm[l*Hc + c] = sm + bm1[l*Hc + c];
        g_bco[l*Hc + c] = sco + bo1[l*Hc + c];
    }
}

// ---------------- h0 (16 rows per block) + sa/da/sm for layer 0 (fma2 packed) ----------------
__global__ __launch_bounds__(256)
void k_h0s(const float* __restrict__ hist, const float* __restrict__ mask,
           const float* __restrict__ Wp, const float* __restrict__ bp,
           const float* __restrict__ Wa1, const float* __restrict__ Wm1){
    int row0 = blockIdx.x * 16;
    int tid = threadIdx.x;
    int c = tid & 127, ty = tid >> 7;
    __shared__ float xs[16*Dc], hs[16*Hc], vmsh[16];
    if(tid < 128) xs[tid] = hist[(size_t)row0*Dc + tid];
    if(tid < 16)  vmsh[tid] = mask[row0 + tid] > 0.f ? 1.f : 0.f;
    __syncthreads();
    float acc[8];
    #pragma unroll
    for(int p = 0; p < 8; p++) acc[p] = bp[c];
    #pragma unroll
    for(int d = 0; d < Dc; d++){
        float w = Wp[d*Hc + c];
        #pragma unroll
        for(int p = 0; p < 8; p++) acc[p] += xs[(ty*8+p)*Dc + d] * w;
    }
    #pragma unroll
    for(int p = 0; p < 8; p++){
        int r = ty*8 + p;
        float h = acc[p] * vmsh[r];
        hs[r*Hc + c] = h;
        g_h[(size_t)(row0+r)*Hc + c] = h;
    }
    __syncthreads();
    // sadam with packed f32x2: thread owns c-pair c0=(tid&63)*2, rows (tid>>6)*4 + p
    int cp = tid & 63, c0 = cp*2, ty2 = tid >> 6;
    const float* was = Wa1;
    const float* wad = was + Hc*Hc;
    const float* wms = Wm1;
    unsigned long long aa[4], dd[4], mm[4];
    #pragma unroll
    for(int p = 0; p < 4; p++){ aa[p]=0ull; dd[p]=0ull; mm[p]=0ull; }
    #pragma unroll 2
    for(int k = 0; k < Hc; k++){
        float2 w1 = *(const float2*)&was[k*Hc + c0];
        float2 w2 = *(const float2*)&wad[k*Hc + c0];
        float2 w3 = *(const float2*)&wms[k*Hc + c0];
        unsigned long long w1p = pack2(w1.x,w1.y), w2p = pack2(w2.x,w2.y), w3p = pack2(w3.x,w3.y);
        #pragma unroll
        for(int p = 0; p < 4; p++){
            float h = hs[(ty2*4+p)*Hc + k];
            unsigned long long hp = pack2(h,h);
            fma2(aa[p], hp, w1p); fma2(dd[p], hp, w2p); fma2(mm[p], hp, w3p);
        }
    }
    #pragma unroll
    for(int p = 0; p < 4; p++){
        size_t r = (size_t)(row0 + ty2*4 + p)*Hc + c0;
        float lo, hi;
        unpack2(aa[p], lo, hi); *(float2*)&g_sa[r] = make_float2(lo, hi);
        unpack2(dd[p], lo, hi); *(float2*)&g_da[r] = make_float2(lo, hi);
        unpack2(mm[p], lo, hi); *(float2*)&g_sm[r] = make_float2(lo, hi);
    }
}

// ---------------- main fused kernel (UNCHANGED from R12 best) ----------------
extern __shared__ char dsmc[];

__global__ __launch_bounds__(512, 2)
void k_main11(int l, const float* __restrict__ hist, const float* __restrict__ mask,
              const float* __restrict__ We1, const float* __restrict__ be1,
              const float* __restrict__ wa2, const float* __restrict__ ba2){
    __shared__ float we1s[4*Hc], be1s[Hc], sab[Hc], smb[Hc], wa2s[Hc];
    __shared__ float attp[4][Lc], wsoft[Lc], red[8], redp[4][Hc];

    int bi = blockIdx.x;
    int b = bi >> 7, i = bi & 127;
    int tid = threadIdx.x;
    int wid = tid >> 5, lane = tid & 31;
    int j = tid & 127;

    {
        const char* wsrc = (const char*)(g_Wbf + (size_t)l*2*TILE_ELEMS);
        char* wdst = dsmc + TILE_BYTES;
        #pragma unroll
        for(int q = 0; q < 8; q++){
            int off = (q*512 + tid)*16;
            cp16(wdst + off, wsrc + off);
        }
        if(tid < 256) cp16(wdst + (4096 + tid)*16, wsrc + (4096 + tid)*16);
        asm volatile("cp.async.commit_group;" ::: "memory");
    }

    if(tid < 128){
        #pragma unroll
        for(int q = 0; q < 4; q++) we1s[q*Hc + tid] = We1[l*4*Hc + q*Hc + tid];
        be1s[tid] = be1[l*Hc + tid];
        sab[tid]  = g_sa[(size_t)bi*Hc + tid] + g_ba[l*Hc + tid];
        smb[tid]  = g_sm[(size_t)bi*Hc + tid] + g_bm[l*Hc + tid];
        wa2s[tid] = wa2[l*Hc + tid];
    }

    const float* hb_ = hist + (size_t)b*Lc*Dc;
    float vldj, vi;
    {
        float lat_i = hb_[i*Dc + 0], lon_i = hb_[i*Dc + 1], src_i = hb_[i*Dc + 6];
        float ts_i = g_ts[b*Lc + i];
        float latj = hb_[j*Dc + 0], lonj = hb_[j*Dc + 1], srcj = hb_[j*Dc + 6];
        float tsj = g_ts[b*Lc + j];
        float dl = lat_i - latj, dn = lon_i - lonj;
        float dist = sqrtf(dl*dl + dn*dn + 1e-8f);
        float dtv = fabsf(ts_i - tsj) * (1.f/300.f);
        float ssv = (src_i == srcj) ? 1.f : 0.f;
        float diag = (j == i) ? 1.f : 0.f;
        vldj = (mask[b*Lc + j] > 0.f) ? 1.f : 0.f;
        vi   = (mask[b*Lc + i] > 0.f) ? 1.f : 0.f;
        __syncthreads();

        int q = tid >> 7;
        char* Th = dsmc + (size_t)j*272;
        #pragma unroll
        for(int kk = 0; kk < 16; kk++){
            int k = q*32 + kk*2;
            float v0 = fmaxf(dist*we1s[k]   + dtv*we1s[Hc+k]   + ssv*we1s[2*Hc+k]   + diag*we1s[3*Hc+k]   + be1s[k],   0.f);
            float v1 = fmaxf(dist*we1s[k+1] + dtv*we1s[Hc+k+1] + ssv*we1s[2*Hc+k+1] + diag*we1s[3*Hc+k+1] + be1s[k+1], 0.f);
            *(uint32_t*)(Th + k*2) = packbf2(v0, v1);
        }
    }
    asm volatile("cp.async.wait_group 0;" ::: "memory");
    __syncthreads();

    int jb = wid & 3, cb = wid >> 2;
    int jt = jb*32, ch = cb*32;
    uint32_t base = smem_u32(dsmc);
    uint32_t aT0 = base + (uint32_t)((jt + (lane & 15))*272 + ((lane >> 4) << 4));
    uint32_t aT1 = aT0 + 16*272;
    uint32_t wBa = base + (uint32_t)(TILE_BYTES   + (lane & 15)*272 + ch*2 + ((lane >> 4) << 4));
    uint32_t wBm = wBa + (uint32_t)TILE_BYTES;
    int gq = lane >> 2, tq = lane & 3;

    float acc[32];

    // PHASE A: attention GEMM
    #pragma unroll
    for(int q = 0; q < 32; q++) acc[q] = 0.f;
    #pragma unroll
    for(int ks = 0; ks < 8; ks++){
        uint32_t a0,a1,a2,a3, c0,c1,c2,c3;
        ldsm4(a0,a1,a2,a3, aT0 + ks*32);
        ldsm4(c0,c1,c2,c3, aT1 + ks*32);
        uint32_t wrow = wBa + ks*4352;
        uint32_t B0,B1,B2,B3, B4,B5,B6,B7;
        ldsm4t(B0,B1,B2,B3, wrow);
        ldsm4t(B4,B5,B6,B7, wrow + 32);
        mma16816(acc+0,  a0,a1,a2,a3, B0,B1);
        mma16816(acc+4,  a0,a1,a2,a3, B2,B3);
        mma16816(acc+8,  a0,a1,a2,a3, B4,B5);
        mma16816(acc+12, a0,a1,a2,a3, B6,B7);
        mma16816(acc+16, c0,c1,c2,c3, B0,B1);
        mma16816(acc+20, c0,c1,c2,c3, B2,B3);
        mma16816(acc+24, c0,c1,c2,c3, B4,B5);
        mma16816(acc+28, c0,c1,c2,c3, B6,B7);
    }
    #pragma unroll
    for(int t16 = 0; t16 < 2; t16++){
        int jA = jt + t16*16 + gq, jB = jA + 8;
        const float* daA = g_da + ((size_t)(b*Lc + jA))*Hc;
        const float* daB = daA + 8*Hc;
        float sA = 0.f, sB = 0.f;
        #pragma unroll
        for(int nq = 0; nq < 4; nq++){
            int c0 = ch + nq*8 + tq*2;
            const float* d = acc + t16*16 + nq*4;
            float2 dA = *(const float2*)(daA + c0);
            float2 dB = *(const float2*)(daB + c0);
            sA += wa2s[c0]  *tanh_fast(sab[c0]  + dA.x + d[0]);
            sA += wa2s[c0+1]*tanh_fast(sab[c0+1]+ dA.y + d[1]);
            sB += wa2s[c0]  *tanh_fast(sab[c0]  + dB.x + d[2]);
            sB += wa2s[c0+1]*tanh_fast(sab[c0+1]+ dB.y + d[3]);
        }
        sA += __shfl_xor_sync(0xffffffffu, sA, 1);
        sA += __shfl_xor_sync(0xffffffffu, sA, 2);
        sB += __shfl_xor_sync(0xffffffffu, sB, 1);
        sB += __shfl_xor_sync(0xffffffffu, sB, 2);
        if(tq == 0){ attp[cb][jA] = sA; attp[cb][jB] = sB; }
    }

    // PHASE B: message GEMM (independent of softmax)
    #pragma unroll
    for(int q = 0; q < 32; q++) acc[q] = 0.f;
    #pragma unroll
    for(int ks = 0; ks < 8; ks++){
        uint32_t a0,a1,a2,a3, c0,c1,c2,c3;
        ldsm4(a0,a1,a2,a3, aT0 + ks*32);
        ldsm4(c0,c1,c2,c3, aT1 + ks*32);
        uint32_t wrow = wBm + ks*4352;
        uint32_t B0,B1,B2,B3, B4,B5,B6,B7;
        ldsm4t(B0,B1,B2,B3, wrow);
        ldsm4t(B4,B5,B6,B7, wrow + 32);
        mma16816(acc+0,  a0,a1,a2,a3, B0,B1);
        mma16816(acc+4,  a0,a1,a2,a3, B2,B3);
        mma16816(acc+8,  a0,a1,a2,a3, B4,B5);
        mma16816(acc+12, a0,a1,a2,a3, B6,B7);
        mma16816(acc+16, c0,c1,c2,c3, B0,B1);
        mma16816(acc+20, c0,c1,c2,c3, B2,B3);
        mma16816(acc+24, c0,c1,c2,c3, B4,B5);
        mma16816(acc+28, c0,c1,c2,c3, B6,B7);
    }
    __syncthreads();

    // softmax over j
    const float inv = 0.088388347648318440550f;
    float sc = -1e9f, e = 0.f;
    if(tid < 128){
        float a = (attp[0][tid] + attp[1][tid] + attp[2][tid] + attp[3][tid] + ba2[l]) * inv;
        bool ok = (vldj > 0.f) && (vi > 0.f);
        sc = ok ? a : -1e9f;
        float m = sc;
        #pragma unroll
        for(int s2 = 16; s2 > 0; s2 >>= 1) m = fmaxf(m, __shfl_xor_sync(0xffffffffu, m, s2));
        if((tid & 31) == 0) red[tid >> 5] = m;
    }
    __syncthreads();
    float bmax = fmaxf(fmaxf(red[0], red[1]), fmaxf(red[2], red[3]));
    if(tid < 128){
        e = expf(sc - bmax);
        float s2 = e;
        #pragma unroll
        for(int m = 16; m > 0; m >>= 1) s2 += __shfl_xor_sync(0xffffffffu, s2, m);
        if((tid & 31) == 0) red[4 + (tid >> 5)] = s2;
    }
    __syncthreads();
    if(tid < 128){
        float tot = red[4]+red[5]+red[6]+red[7];
        wsoft[tid] = e / tot;
    }
    __syncthreads();

    // message epilogue
    float* su = (float*)dsmc;
    {
        float v[8];
        #pragma unroll
        for(int p = 0; p < 8; p++) v[p] = 0.f;
        #pragma unroll
        for(int t16 = 0; t16 < 2; t16++){
            int jA = jt + t16*16 + gq, jB = jA + 8;
            float wA = wsoft[jA], wB2 = wsoft[jB];
            #pragma unroll
            for(int nq = 0; nq < 4; nq++){
                int c0 = ch + nq*8 + tq*2;
                const float* d = acc + t16*16 + nq*4;
                v[nq*2]   += wA*fmaxf(smb[c0]  + d[0], 0.f) + wB2*fmaxf(smb[c0]  + d[2], 0.f);
                v[nq*2+1] += wA*fmaxf(smb[c0+1]+ d[1], 0.f) + wB2*fmaxf(smb[c0+1]+ d[3], 0.f);
            }
        }
        int p = jb*8 + gq;
        #pragma unroll
        for(int nq = 0; nq < 4; nq++){
            int c0 = ch + nq*8 + tq*2;
            *(float2*)(su + p*130 + c0) = make_float2(v[nq*2], v[nq*2+1]);
        }
    }
    __syncthreads();
    {
        int qq = tid >> 7, c = tid & 127;
        float s = 0.f;
        #pragma unroll
        for(int r = 0; r < 8; r++) s += su[(qq*8 + r)*130 + c];
        redp[qq][c] = s;
    }
    __syncthreads();
    if(tid < 128){
        g_aggpre[(size_t)bi*Hc + tid] = redp[0][tid] + redp[1][tid] + redp[2][tid] + redp[3][tid];
    }
}

// ---------------- epilogue per 16 rows: fma2 packed, Wm2 folded ----------------
__global__ __launch_bounds__(512)
void k_post3(int l, int has_next, const float* __restrict__ mask,
             const float* __restrict__ Wo1,
             const float* __restrict__ Wo2, const float* __restrict__ bo2,
             const float* __restrict__ lng, const float* __restrict__ lnb,
             const float* __restrict__ Wa1, const float* __restrict__ Wm1){
    int row0 = blockIdx.x * 16;
    int tid = threadIdx.x;
    __shared__ float hs[16*Hc], as_[16*Hc], op1[16*Hc], xs[16*Hc];
    __shared__ float mu[16], rsd[16], vmsh[16];

    #pragma unroll
    for(int q = 0; q < 4; q++){
        int idx = q*512 + tid;
        hs[idx]  = g_h[(size_t)row0*Hc + idx];
        as_[idx] = g_aggpre[(size_t)row0*Hc + idx];
    }
    if(tid < 16) vmsh[tid] = mask[row0 + tid] > 0.f ? 1.f : 0.f;
    __syncthreads();

    int cp = tid & 63, c0 = cp*2, ty = tid >> 6;   // ty 0..7, rows ty*2 + {0,1}
    int r0 = ty*2, r1 = r0 + 1;

    // stage 1: op1 = relu(h@Wo1h + aggpre@Wco + bco)
    {
        const float* wo1h = Wo1 + l*2*Hc*Hc;
        const float* wco  = g_Wco + l*Hc*Hc;
        float2 bb = *(const float2*)&g_bco[l*Hc + c0];
        unsigned long long a0 = pack2(bb.x, bb.y), a1 = a0;
        #pragma unroll 2
        for(int k = 0; k < Hc; k++){
            float2 w1 = *(const float2*)&wo1h[k*Hc + c0];
            float2 w2 = *(const float2*)&wco[k*Hc + c0];
            unsigned long long w1p = pack2(w1.x,w1.y), w2p = pack2(w2.x,w2.y);
            float h0 = hs[r0*Hc + k], h1 = hs[r1*Hc + k];
            float g0 = as_[r0*Hc + k], g1 = as_[r1*Hc + k];
            fma2(a0, pack2(h0,h0), w1p); fma2(a0, pack2(g0,g0), w2p);
            fma2(a1, pack2(h1,h1), w1p); fma2(a1, pack2(g1,g1), w2p);
        }
        float lo, hi;
        unpack2(a0, lo, hi); op1[r0*Hc + c0] = fmaxf(lo,0.f); op1[r0*Hc + c0+1] = fmaxf(hi,0.f);
        unpack2(a1, lo, hi); op1[r1*Hc + c0] = fmaxf(lo,0.f); op1[r1*Hc + c0+1] = fmaxf(hi,0.f);
    }
    __syncthreads();

    // stage 2: x = h + op1@Wo2 + bo2
    {
        const float* wo2 = Wo2 + l*Hc*Hc;
        float2 bb = *(const float2*)&bo2[l*Hc + c0];
        unsigned long long a0 = pack2(bb.x, bb.y), a1 = a0;
        #pragma unroll 2
        for(int k = 0; k < Hc; k++){
            float2 w = *(const float2*)&wo2[k*Hc + c0];
            unsigned long long wp = pack2(w.x,w.y);
            float o0 = op1[r0*Hc + k], o1 = op1[r1*Hc + k];
            fma2(a0, pack2(o0,o0), wp);
            fma2(a1, pack2(o1,o1), wp);
        }
        float lo, hi;
        unpack2(a0, lo, hi);
        xs[r0*Hc + c0]   = hs[r0*Hc + c0]   + lo;
        xs[r0*Hc + c0+1] = hs[r0*Hc + c0+1] + hi;
        unpack2(a1, lo, hi);
        xs[r1*Hc + c0]   = hs[r1*Hc + c0]   + lo;
        xs[r1*Hc + c0+1] = hs[r1*Hc + c0+1] + hi;
    }
    __syncthreads();

    // LayerNorm per row (first 256 threads)
    if(tid < 256){
        int row = tid >> 4, l16 = tid & 15;
        float s = 0.f, s2 = 0.f;
        #pragma unroll
        for(int q = 0; q < 8; q++){
            float v = xs[row*Hc + l16 + q*16];
            s += v; s2 += v*v;
        }
        #pragma unroll
        for(int m = 8; m > 0; m >>= 1){
            s  += __shfl_xor_sync(0xffffffffu, s, m);
            s2 += __shfl_xor_sync(0xffffffffu, s2, m);
        }
        if(l16 == 0){
            float m_ = s * (1.f/128.f);
            mu[row] = m_;
            rsd[row] = rsqrtf(s2 * (1.f/128.f) - m_*m_ + 1e-5f);
        }
    }
    __syncthreads();
    {
        const float* lg = lng + l*Hc;
        const float* lb = lnb + l*Hc;
        #pragma unroll
        for(int p = 0; p < 2; p++){
            int r = r0 + p;
            #pragma unroll
            for(int q = 0; q < 2; q++){
                int c = c0 + q;
                float x = xs[r*Hc + c];
                float hn = ((x - mu[r]) * rsd[r] * lg[c] + lb[c]) * vmsh[r];
                g_h[(size_t)(row0+r)*Hc + c] = hn;
                hs[r*Hc + c] = hn;
            }
        }
    }

    // stage 3: next-layer sa/da/sm
    if(has_next){
        __syncthreads();
        int ln = l + 1;
        const float* was = Wa1 + ln*3*Hc*Hc;
        const float* wad = was + Hc*Hc;
        const float* wms = Wm1 + ln*2*Hc*Hc;
        unsigned long long aa0=0ull, aa1=0ull, dd0=0ull, dd1=0ull, mm0=0ull, mm1=0ull;
        #pragma unroll 2
        for(int k = 0; k < Hc; k++){
            float2 w1 = *(const float2*)&was[k*Hc + c0];
            float2 w2 = *(const float2*)&wad[k*Hc + c0];
            float2 w3 = *(const float2*)&wms[k*Hc + c0];
            unsigned long long w1p = pack2(w1.x,w1.y), w2p = pack2(w2.x,w2.y), w3p = pack2(w3.x,w3.y);
            float h0 = hs[r0*Hc + k], h1 = hs[r1*Hc + k];
            unsigned long long h0p = pack2(h0,h0), h1p = pack2(h1,h1);
            fma2(aa0, h0p, w1p); fma2(dd0, h0p, w2p); fma2(mm0, h0p, w3p);
            fma2(aa1, h1p, w1p); fma2(dd1, h1p, w2p); fma2(mm1, h1p, w3p);
        }
        float lo, hi;
        size_t b0 = (size_t)(row0 + r0)*Hc + c0;
        size_t b1 = (size_t)(row0 + r1)*Hc + c0;
        unpack2(aa0, lo, hi); *(float2*)&g_sa[b0] = make_float2(lo, hi);
        unpack2(aa1, lo, hi); *(float2*)&g_sa[b1] = make_float2(lo, hi);
        unpack2(dd0, lo, hi); *(float2*)&g_da[b0] = make_float2(lo, hi);
        unpack2(dd1, lo, hi); *(float2*)&g_da[b1] = make_float2(lo, hi);
        unpack2(mm0, lo, hi); *(float2*)&g_sm[b0] = make_float2(lo, hi);
        unpack2(mm1, lo, hi); *(float2*)&g_sm[b1] = make_float2(lo, hi);
    }
}

// ---------------- decoder (+ fused h copy) ----------------
__global__ void k_dec2(const float* __restrict__ hist, const float* __restrict__ mask,
                       const float* __restrict__ hg, const float* __restrict__ hb,
                       const float* __restrict__ Wh1, const float* __restrict__ bh1,
                       const float* __restrict__ Wh2, const float* __restrict__ bh2,
                       float* __restrict__ out){
    if(blockIdx.x >= 16){
        int i = (blockIdx.x - 16)*128 + threadIdx.x;
        out[384 + i] = g_h[i];
        return;
    }
    int b = blockIdx.x; int t = threadIdx.x;
    __shared__ float x[136], xn[136], hid[Hc];
    __shared__ float red2[4];
    float mv = mask[b*Lc + t];
    float s = mv;
    #pragma unroll
    for(int sft = 16; sft > 0; sft >>= 1) s += __shfl_xor_sync(0xffffffffu, s, sft);
    if((t & 31) == 0) red2[t >> 5] = s;
    __syncthreads();
    float tot = red2[0]+red2[1]+red2[2]+red2[3];
    int vc = (int)tot;
    vc = min(max(vc, 1), Lc);
    int last = vc - 1;

    if(t < Dc) x[t] = hist[((size_t)b*Lc + last)*Dc + t];
    x[Dc + t] = g_h[((size_t)b*Lc + last)*Hc + t];
    __syncthreads();
    float s1 = x[t] + ((t < 8) ? x[128 + t] : 0.f);
    #pragma unroll
    for(int sft = 16; sft > 0; sft >>= 1) s1 += __shfl_xor_sync(0xffffffffu, s1, sft);
    __syncthreads();
    if((t & 31) == 0) red2[t >> 5] = s1;
    __syncthreads();
    float mu = (red2[0]+red2[1]+red2[2]+red2[3]) * (1.f/136.f);
    float d0 = x[t] - mu;
    float s2 = d0*d0;
    if(t < 8){ float d1 = x[128 + t] - mu; s2 += d1*d1; }
    #pragma unroll
    for(int sft = 16; sft > 0; sft >>= 1) s2 += __shfl_xor_sync(0xffffffffu, s2, sft);
    __syncthreads();
    if((t & 31) == 0) red2[t >> 5] = s2;
    __syncthreads();
    float rs = rsqrtf((red2[0]+red2[1]+red2[2]+red2[3]) * (1.f/136.f) + 1e-5f);
    xn[t] = (x[t] - mu) * rs * hg[t] + hb[t];
    if(t < 8) xn[128 + t] = (x[128 + t] - mu) * rs * hg[128 + t] + hb[128 + t];
    __syncthreads();
    float h_ = bh1[t];
    for(int k = 0; k < 136; k++) h_ += xn[k]*Wh1[k*Hc + t];
    hid[t] = fmaxf(h_, 0.f);
    __syncthreads();
    if(t < 24){
        float p = bh2[t];
        for(int k = 0; k < Hc; k++) p += hid[k]*Wh2[k*24 + t];
        if(isnan(p)) p = 0.f;
        else if(isinf(p)) p = (p > 0.f) ? 1e4f : -1e4f;
        out[b*24 + t] = p;
    }
}

// ---------------- launch ----------------
extern "C" void kernel_launch(void* const* d_in, const int* in_sizes, int n_in,
                              void* d_out, int out_size){
    const float* hist = (const float*)d_in[0];
    const float* mask = (const float*)d_in[1];
    const float* Wp   = (const float*)d_in[2];
    const float* bp   = (const float*)d_in[3];
    const float* We1  = (const float*)d_in[4];
    const float* be1  = (const float*)d_in[5];
    const float* We2  = (const float*)d_in[6];
    const float* be2  = (const float*)d_in[7];
    const float* Wa1  = (const float*)d_in[8];
    const float* ba1  = (const float*)d_in[9];
    const float* wa2  = (const float*)d_in[10];
    const float* ba2  = (const float*)d_in[11];
    const float* Wm1  = (const float*)d_in[12];
    const float* bm1  = (const float*)d_in[13];
    const float* Wm2  = (const float*)d_in[14];
    const float* bm2  = (const float*)d_in[15];
    const float* Wo1  = (const float*)d_in[16];
    const float* bo1  = (const float*)d_in[17];
    const float* Wo2  = (const float*)d_in[18];
    const float* bo2  = (const float*)d_in[19];
    const float* lng  = (const float*)d_in[20];
    const float* lnb  = (const float*)d_in[21];
    const float* hg   = (const float*)d_in[22];
    const float* hbv  = (const float*)d_in[23];
    const float* Wh1  = (const float*)d_in[24];
    const float* bh1  = (const float*)d_in[25];
    const float* Wh2  = (const float*)d_in[26];
    const float* bh2  = (const float*)d_in[27];
    float* out = (float*)d_out;

    cudaFuncSetAttribute(k_main11, cudaFuncAttributeMaxDynamicSharedMemorySize, 3*TILE_BYTES);

    k_ts2<<<Bc, 128>>>(hist);
    k_prepwb<<<NLc*129, Hc>>>(We2, be2, Wa1, Wm1, ba1, bm1, Wm2, bm2, Wo1, bo1);
    k_h0s<<<Bc*Lc/16, 256>>>(hist, mask, Wp, bp, Wa1, Wm1);
    for(int l = 0; l < NLc; l++){
        k_main11<<<Bc*Lc, 512, 3*TILE_BYTES>>>(l, hist, mask, We1, be1, wa2, ba2);
        k_post3<<<Bc*Lc/16, 512>>>(l, (l+1 < NLc) ? 1 : 0, mask,
                                   Wo1, Wo2, bo2, lng, lnb, Wa1, Wm1);
    }
    int do_copy = (out_size >= 384 + Bc*Lc*Hc) ? 1 : 0;
    k_dec2<<<16 + (do_copy ? (Bc*Lc*Hc)/128 : 0), 128>>>(hist, mask, hg, hbv, Wh1, bh1, Wh2, bh2, out);
}

// round 15
// speedup vs baseline: 1.1007x; 1.1007x over previous
#include <cuda_runtime.h>
#include <cuda_bf16.h>
#include <math.h>
#include <stdint.h>

#define Bc 16
#define Lc 128
#define Dc 8
#define Hc 128
#define NLc 2

// bf16 tile geometry: [128 rows][136 cols] bf16, pitch 272B
#define WPITCH 136
#define TILE_ELEMS (128*WPITCH)          // 17408
#define TILE_BYTES (TILE_ELEMS*2)        // 34816

// ---------------- scratch (static device globals; no allocation) ----------------
__device__ __align__(16) float g_ts[Bc*Lc];
__device__ __align__(16) float g_h[Bc*Lc*Hc];
__device__ __align__(16) float g_sa[Bc*Lc*Hc];
__device__ __align__(16) float g_da[Bc*Lc*Hc];
__device__ __align__(16) float g_sm[Bc*Lc*Hc];
__device__ __align__(16) float g_aggpre[Bc*Lc*Hc];
__device__ __align__(16) float g_ba[NLc*Hc];
__device__ __align__(16) float g_bm[NLc*Hc];
__device__ __align__(16) float g_Wco[NLc*Hc*Hc];   // Wm2 @ Wo1a folded
__device__ __align__(16) float g_bco[NLc*Hc];      // bm2 @ Wo1a + bo1
// folded weights as bf16, [k][c] rows padded to 136: per layer Wa | Wm
__device__ __align__(16) __nv_bfloat16 g_Wbf[NLc*2*TILE_ELEMS];

// ---------------- helpers ----------------
__device__ __forceinline__ uint32_t smem_u32(const void* p){
    uint32_t a;
    asm("{ .reg .u64 t; cvta.to.shared.u64 t, %1; cvt.u32.u64 %0, t; }" : "=r"(a) : "l"(p));
    return a;
}
__device__ __forceinline__ void cp16(void* dst_smem, const void* src){
    unsigned sdst = (unsigned)__cvta_generic_to_shared(dst_smem);
    asm volatile("cp.async.cg.shared.global [%0], [%1], 16;" :: "r"(sdst), "l"(src));
}
__device__ __forceinline__ float tanh_fast(float x){
    float r; asm("tanh.approx.f32 %0, %1;" : "=f"(r) : "f"(x)); return r;
}
__device__ __forceinline__ void ldsm4(uint32_t &r0,uint32_t &r1,uint32_t &r2,uint32_t &r3,uint32_t a){
    asm volatile("ldmatrix.sync.aligned.m8n8.x4.shared.b16 {%0,%1,%2,%3},[%4];"
        : "=r"(r0),"=r"(r1),"=r"(r2),"=r"(r3) : "r"(a));
}
__device__ __forceinline__ void ldsm4t(uint32_t &r0,uint32_t &r1,uint32_t &r2,uint32_t &r3,uint32_t a){
    asm volatile("ldmatrix.sync.aligned.m8n8.x4.trans.shared.b16 {%0,%1,%2,%3},[%4];"
        : "=r"(r0),"=r"(r1),"=r"(r2),"=r"(r3) : "r"(a));
}
__device__ __forceinline__ void mma16816(float* d, uint32_t a0,uint32_t a1,uint32_t a2,uint32_t a3,
                                         uint32_t b0,uint32_t b1){
    asm volatile("mma.sync.aligned.m16n8k16.row.col.f32.bf16.bf16.f32 "
        "{%0,%1,%2,%3},{%4,%5,%6,%7},{%8,%9},{%0,%1,%2,%3};"
        : "+f"(d[0]),"+f"(d[1]),"+f"(d[2]),"+f"(d[3])
        : "r"(a0),"r"(a1),"r"(a2),"r"(a3),"r"(b0),"r"(b1));
}
// pack two floats to bf16x2 (v0 -> low half, v1 -> high)
__device__ __forceinline__ uint32_t packbf2(float v0, float v1){
    uint32_t r; asm("cvt.rn.bf16x2.f32 %0, %1, %2;" : "=r"(r) : "f"(v1), "f"(v0)); return r;
}

// ---------------- parallel cumsum of ts ----------------
__global__ __launch_bounds__(128)
void k_ts2(const float* __restrict__ hist){
    int b = blockIdx.x;
    int t = threadIdx.x;
    int lane = t & 31, w = t >> 5;
    __shared__ float wsum[4];
    float v = fmaxf(hist[(b*Lc + t)*Dc + 5], 0.f);
    float s = v;
    #pragma unroll
    for(int d = 1; d < 32; d <<= 1){
        float o = __shfl_up_sync(0xffffffffu, s, d);
        if(lane >= d) s += o;
    }
    if(lane == 31) wsum[w] = s;
    __syncthreads();
    float pre = 0.f;
    #pragma unroll
    for(int q = 0; q < 4; q++) pre += (q < w) ? wsum[q] : 0.f;
    g_ts[b*Lc + t] = s + pre;
}

// ---------------- folded weights -> bf16 tiles + Wco/bco fold ----------------
__global__ void k_prepwb(const float* __restrict__ We2, const float* __restrict__ be2,
                         const float* __restrict__ Wa1, const float* __restrict__ Wm1,
                         const float* __restrict__ ba1, const float* __restrict__ bm1,
                         const float* __restrict__ Wm2, const float* __restrict__ bm2,
                         const float* __restrict__ Wo1, const float* __restrict__ bo1){
    int l = blockIdx.x / 129, kk = blockIdx.x % 129;
    int c = threadIdx.x;
    __shared__ float ws[Hc], ws2[Hc];
    if(kk < Hc){
        ws[c]  = We2[l*Hc*Hc + kk*Hc + c];
        ws2[c] = Wm2[l*Hc*Hc + kk*Hc + c];
    } else {
        ws[c]  = be2[l*Hc + c];
        ws2[c] = bm2[l*Hc + c];
    }
    __syncthreads();
    const float* wa  = Wa1 + l*3*Hc*Hc + 2*Hc*Hc;
    const float* wm  = Wm1 + l*2*Hc*Hc + Hc*Hc;
    const float* wo1a = Wo1 + l*2*Hc*Hc + Hc*Hc;
    float sa = 0.f, sm = 0.f, sco = 0.f;
    #pragma unroll 4
    for(int r = 0; r < Hc; r++){
        float w = ws[r], w2 = ws2[r];
        sa += w*wa[r*Hc + c]; sm += w*wm[r*Hc + c]; sco += w2*wo1a[r*Hc + c];
    }
    if(kk < Hc){
        __nv_bfloat16* base = g_Wbf + (size_t)l*2*TILE_ELEMS;
        base[             kk*WPITCH + c] = __float2bfloat16(sa);
        base[TILE_ELEMS + kk*WPITCH + c] = __float2bfloat16(sm);
        g_Wco[(l*Hc + kk)*Hc + c] = sco;
    } else {
        g_ba[l*Hc + c] = sa + ba1[l*Hc + c];
        g_bm[l*Hc + c] = sm + bm1[l*Hc + c];
        g_bco[l*Hc + c] = sco + bo1[l*Hc + c];
    }
}

// ---------------- h0 (16 rows per block) + sa/da/sm for layer 0 ----------------
__global__ __launch_bounds__(256)
void k_h0s(const float* __restrict__ hist, const float* __restrict__ mask,
           const float* __restrict__ Wp, const float* __restrict__ bp,
           const float* __restrict__ Wa1, const float* __restrict__ Wm1){
    int row0 = blockIdx.x * 16;
    int tid = threadIdx.x;
    int c = tid & 127, ty = tid >> 7;
    __shared__ float xs[16*Dc], hs[16*Hc], vmsh[16];
    if(tid < 128) xs[tid] = hist[(size_t)row0*Dc + tid];
    if(tid < 16)  vmsh[tid] = mask[row0 + tid] > 0.f ? 1.f : 0.f;
    __syncthreads();
    float acc[8];
    #pragma unroll
    for(int p = 0; p < 8; p++) acc[p] = bp[c];
    #pragma unroll
    for(int d = 0; d < Dc; d++){
        float w = Wp[d*Hc + c];
        #pragma unroll
        for(int p = 0; p < 8; p++) acc[p] += xs[(ty*8+p)*Dc + d] * w;
    }
    #pragma unroll
    for(int p = 0; p < 8; p++){
        int r = ty*8 + p;
        float h = acc[p] * vmsh[r];
        hs[r*Hc + c] = h;
        g_h[(size_t)(row0+r)*Hc + c] = h;
    }
    __syncthreads();
    const float* was = Wa1;
    const float* wad = was + Hc*Hc;
    const float* wms = Wm1;
    float aa[8], dd[8], mm[8];
    #pragma unroll
    for(int p = 0; p < 8; p++){ aa[p]=0.f; dd[p]=0.f; mm[p]=0.f; }
    #pragma unroll 4
    for(int k = 0; k < Hc; k++){
        float w1 = was[k*Hc + c], w2 = wad[k*Hc + c], w3 = wms[k*Hc + c];
        #pragma unroll
        for(int p = 0; p < 8; p++){
            float h = hs[(ty*8+p)*Hc + k];
            aa[p] += h*w1; dd[p] += h*w2; mm[p] += h*w3;
        }
    }
    #pragma unroll
    for(int p = 0; p < 8; p++){
        size_t r = (size_t)(row0 + ty*8 + p)*Hc + c;
        g_sa[r] = aa[p]; g_da[r] = dd[p]; g_sm[r] = mm[p];
    }
}

// ---------------- main fused kernel (UNCHANGED — proven best) ----------------
extern __shared__ char dsmc[];

__global__ __launch_bounds__(512, 2)
void k_main11(int l, const float* __restrict__ hist, const float* __restrict__ mask,
              const float* __restrict__ We1, const float* __restrict__ be1,
              const float* __restrict__ wa2, const float* __restrict__ ba2){
    __shared__ float we1s[4*Hc], be1s[Hc], sab[Hc], smb[Hc], wa2s[Hc];
    __shared__ float attp[4][Lc], wsoft[Lc], red[8], redp[4][Hc];

    int bi = blockIdx.x;
    int b = bi >> 7, i = bi & 127;
    int tid = threadIdx.x;
    int wid = tid >> 5, lane = tid & 31;
    int j = tid & 127;

    {
        const char* wsrc = (const char*)(g_Wbf + (size_t)l*2*TILE_ELEMS);
        char* wdst = dsmc + TILE_BYTES;
        #pragma unroll
        for(int q = 0; q < 8; q++){
            int off = (q*512 + tid)*16;
            cp16(wdst + off, wsrc + off);
        }
        if(tid < 256) cp16(wdst + (4096 + tid)*16, wsrc + (4096 + tid)*16);
        asm volatile("cp.async.commit_group;" ::: "memory");
    }

    if(tid < 128){
        #pragma unroll
        for(int q = 0; q < 4; q++) we1s[q*Hc + tid] = We1[l*4*Hc + q*Hc + tid];
        be1s[tid] = be1[l*Hc + tid];
        sab[tid]  = g_sa[(size_t)bi*Hc + tid] + g_ba[l*Hc + tid];
        smb[tid]  = g_sm[(size_t)bi*Hc + tid] + g_bm[l*Hc + tid];
        wa2s[tid] = wa2[l*Hc + tid];
    }

    const float* hb_ = hist + (size_t)b*Lc*Dc;
    float vldj, vi;
    {
        float lat_i = hb_[i*Dc + 0], lon_i = hb_[i*Dc + 1], src_i = hb_[i*Dc + 6];
        float ts_i = g_ts[b*Lc + i];
        float latj = hb_[j*Dc + 0], lonj = hb_[j*Dc + 1], srcj = hb_[j*Dc + 6];
        float tsj = g_ts[b*Lc + j];
        float dl = lat_i - latj, dn = lon_i - lonj;
        float dist = sqrtf(dl*dl + dn*dn + 1e-8f);
        float dtv = fabsf(ts_i - tsj) * (1.f/300.f);
        float ssv = (src_i == srcj) ? 1.f : 0.f;
        float diag = (j == i) ? 1.f : 0.f;
        vldj = (mask[b*Lc + j] > 0.f) ? 1.f : 0.f;
        vi   = (mask[b*Lc + i] > 0.f) ? 1.f : 0.f;
        __syncthreads();

        int q = tid >> 7;
        char* Th = dsmc + (size_t)j*272;
        #pragma unroll
        for(int kk = 0; kk < 16; kk++){
            int k = q*32 + kk*2;
            float v0 = fmaxf(dist*we1s[k]   + dtv*we1s[Hc+k]   + ssv*we1s[2*Hc+k]   + diag*we1s[3*Hc+k]   + be1s[k],   0.f);
            float v1 = fmaxf(dist*we1s[k+1] + dtv*we1s[Hc+k+1] + ssv*we1s[2*Hc+k+1] + diag*we1s[3*Hc+k+1] + be1s[k+1], 0.f);
            *(uint32_t*)(Th + k*2) = packbf2(v0, v1);
        }
    }
    asm volatile("cp.async.wait_group 0;" ::: "memory");
    __syncthreads();

    int jb = wid & 3, cb = wid >> 2;
    int jt = jb*32, ch = cb*32;
    uint32_t base = smem_u32(dsmc);
    uint32_t aT0 = base + (uint32_t)((jt + (lane & 15))*272 + ((lane >> 4) << 4));
    uint32_t aT1 = aT0 + 16*272;
    uint32_t wBa = base + (uint32_t)(TILE_BYTES   + (lane & 15)*272 + ch*2 + ((lane >> 4) << 4));
    uint32_t wBm = wBa + (uint32_t)TILE_BYTES;
    int gq = lane >> 2, tq = lane & 3;

    float acc[32];

    // PHASE A: attention GEMM
    #pragma unroll
    for(int q = 0; q < 32; q++) acc[q] = 0.f;
    #pragma unroll
    for(int ks = 0; ks < 8; ks++){
        uint32_t a0,a1,a2,a3, c0,c1,c2,c3;
        ldsm4(a0,a1,a2,a3, aT0 + ks*32);
        ldsm4(c0,c1,c2,c3, aT1 + ks*32);
        uint32_t wrow = wBa + ks*4352;
        uint32_t B0,B1,B2,B3, B4,B5,B6,B7;
        ldsm4t(B0,B1,B2,B3, wrow);
        ldsm4t(B4,B5,B6,B7, wrow + 32);
        mma16816(acc+0,  a0,a1,a2,a3, B0,B1);
        mma16816(acc+4,  a0,a1,a2,a3, B2,B3);
        mma16816(acc+8,  a0,a1,a2,a3, B4,B5);
        mma16816(acc+12, a0,a1,a2,a3, B6,B7);
        mma16816(acc+16, c0,c1,c2,c3, B0,B1);
        mma16816(acc+20, c0,c1,c2,c3, B2,B3);
        mma16816(acc+24, c0,c1,c2,c3, B4,B5);
        mma16816(acc+28, c0,c1,c2,c3, B6,B7);
    }
    #pragma unroll
    for(int t16 = 0; t16 < 2; t16++){
        int jA = jt + t16*16 + gq, jB = jA + 8;
        const float* daA = g_da + ((size_t)(b*Lc + jA))*Hc;
        const float* daB = daA + 8*Hc;
        float sA = 0.f, sB = 0.f;
        #pragma unroll
        for(int nq = 0; nq < 4; nq++){
            int c0 = ch + nq*8 + tq*2;
            const float* d = acc + t16*16 + nq*4;
            float2 dA = *(const float2*)(daA + c0);
            float2 dB = *(const float2*)(daB + c0);
            sA += wa2s[c0]  *tanh_fast(sab[c0]  + dA.x + d[0]);
            sA += wa2s[c0+1]*tanh_fast(sab[c0+1]+ dA.y + d[1]);
            sB += wa2s[c0]  *tanh_fast(sab[c0]  + dB.x + d[2]);
            sB += wa2s[c0+1]*tanh_fast(sab[c0+1]+ dB.y + d[3]);
        }
        sA += __shfl_xor_sync(0xffffffffu, sA, 1);
        sA += __shfl_xor_sync(0xffffffffu, sA, 2);
        sB += __shfl_xor_sync(0xffffffffu, sB, 1);
        sB += __shfl_xor_sync(0xffffffffu, sB, 2);
        if(tq == 0){ attp[cb][jA] = sA; attp[cb][jB] = sB; }
    }

    // PHASE B: message GEMM (independent of softmax)
    #pragma unroll
    for(int q = 0; q < 32; q++) acc[q] = 0.f;
    #pragma unroll
    for(int ks = 0; ks < 8; ks++){
        uint32_t a0,a1,a2,a3, c0,c1,c2,c3;
        ldsm4(a0,a1,a2,a3, aT0 + ks*32);
        ldsm4(c0,c1,c2,c3, aT1 + ks*32);
        uint32_t wrow = wBm + ks*4352;
        uint32_t B0,B1,B2,B3, B4,B5,B6,B7;
        ldsm4t(B0,B1,B2,B3, wrow);
        ldsm4t(B4,B5,B6,B7, wrow + 32);
        mma16816(acc+0,  a0,a1,a2,a3, B0,B1);
        mma16816(acc+4,  a0,a1,a2,a3, B2,B3);
        mma16816(acc+8,  a0,a1,a2,a3, B4,B5);
        mma16816(acc+12, a0,a1,a2,a3, B6,B7);
        mma16816(acc+16, c0,c1,c2,c3, B0,B1);
        mma16816(acc+20, c0,c1,c2,c3, B2,B3);
        mma16816(acc+24, c0,c1,c2,c3, B4,B5);
        mma16816(acc+28, c0,c1,c2,c3, B6,B7);
    }
    __syncthreads();

    // softmax over j
    const float inv = 0.088388347648318440550f;
    float sc = -1e9f, e = 0.f;
    if(tid < 128){
        float a = (attp[0][tid] + attp[1][tid] + attp[2][tid] + attp[3][tid] + ba2[l]) * inv;
        bool ok = (vldj > 0.f) && (vi > 0.f);
        sc = ok ? a : -1e9f;
        float m = sc;
        #pragma unroll
        for(int s2 = 16; s2 > 0; s2 >>= 1) m = fmaxf(m, __shfl_xor_sync(0xffffffffu, m, s2));
        if((tid & 31) == 0) red[tid >> 5] = m;
    }
    __syncthreads();
    float bmax = fmaxf(fmaxf(red[0], red[1]), fmaxf(red[2], red[3]));
    if(tid < 128){
        e = expf(sc - bmax);
        float s2 = e;
        #pragma unroll
        for(int m = 16; m > 0; m >>= 1) s2 += __shfl_xor_sync(0xffffffffu, s2, m);
        if((tid & 31) == 0) red[4 + (tid >> 5)] = s2;
    }
    __syncthreads();
    if(tid < 128){
        float tot = red[4]+red[5]+red[6]+red[7];
        wsoft[tid] = e / tot;
    }
    __syncthreads();

    // message epilogue
    float* su = (float*)dsmc;
    {
        float v[8];
        #pragma unroll
        for(int p = 0; p < 8; p++) v[p] = 0.f;
        #pragma unroll
        for(int t16 = 0; t16 < 2; t16++){
            int jA = jt + t16*16 + gq, jB = jA + 8;
            float wA = wsoft[jA], wB2 = wsoft[jB];
            #pragma unroll
            for(int nq = 0; nq < 4; nq++){
                int c0 = ch + nq*8 + tq*2;
                const float* d = acc + t16*16 + nq*4;
                v[nq*2]   += wA*fmaxf(smb[c0]  + d[0], 0.f) + wB2*fmaxf(smb[c0]  + d[2], 0.f);
                v[nq*2+1] += wA*fmaxf(smb[c0+1]+ d[1], 0.f) + wB2*fmaxf(smb[c0+1]+ d[3], 0.f);
            }
        }
        int p = jb*8 + gq;
        #pragma unroll
        for(int nq = 0; nq < 4; nq++){
            int c0 = ch + nq*8 + tq*2;
            *(float2*)(su + p*130 + c0) = make_float2(v[nq*2], v[nq*2+1]);
        }
    }
    __syncthreads();
    {
        int qq = tid >> 7, c = tid & 127;
        float s = 0.f;
        #pragma unroll
        for(int r = 0; r < 8; r++) s += su[(qq*8 + r)*130 + c];
        redp[qq][c] = s;
    }
    __syncthreads();
    if(tid < 128){
        g_aggpre[(size_t)bi*Hc + tid] = redp[0][tid] + redp[1][tid] + redp[2][tid] + redp[3][tid];
    }
}

// ---------------- epilogue per 16 rows: R12 structure + Wco fold (6 matvecs) ----------------
__global__ __launch_bounds__(256)
void k_post4(int l, int has_next, const float* __restrict__ mask,
             const float* __restrict__ Wo1,
             const float* __restrict__ Wo2, const float* __restrict__ bo2,
             const float* __restrict__ lng, const float* __restrict__ lnb,
             const float* __restrict__ Wa1, const float* __restrict__ Wm1){
    int row0 = blockIdx.x * 16;
    int tid = threadIdx.x;
    int c = tid & 127, ty = tid >> 7;
    __shared__ float hs[16*Hc], as_[16*Hc], op1[16*Hc], xs[16*Hc];
    __shared__ float mu[16], rsd[16], vmsh[16];

    #pragma unroll
    for(int q = 0; q < 8; q++){
        int idx = q*256 + tid;
        hs[idx]  = g_h[(size_t)row0*Hc + idx];
        as_[idx] = g_aggpre[(size_t)row0*Hc + idx];
    }
    if(tid < 16) vmsh[tid] = mask[row0 + tid] > 0.f ? 1.f : 0.f;
    __syncthreads();

    float acc[8];
    // stage 1: op1 = relu(h @ Wo1h + aggpre @ Wco + bco)   [Wm2 folded into Wco]
    const float* wo1h = Wo1 + l*2*Hc*Hc;
    const float* wco  = g_Wco + l*Hc*Hc;
    #pragma unroll
    for(int p = 0; p < 8; p++) acc[p] = g_bco[l*Hc + c];
    #pragma unroll 4
    for(int k = 0; k < Hc; k++){
        float w1 = wo1h[k*Hc + c], w2 = wco[k*Hc + c];
        #pragma unroll
        for(int p = 0; p < 8; p++)
            acc[p] += hs[(ty*8+p)*Hc + k]*w1 + as_[(ty*8+p)*Hc + k]*w2;
    }
    #pragma unroll
    for(int p = 0; p < 8; p++) op1[(ty*8+p)*Hc + c] = fmaxf(acc[p], 0.f);
    __syncthreads();

    // stage 2: x = h + op1 @ Wo2 + bo2
    const float* wo2 = Wo2 + l*Hc*Hc;
    #pragma unroll
    for(int p = 0; p < 8; p++) acc[p] = bo2[l*Hc + c];
    #pragma unroll 4
    for(int k = 0; k < Hc; k++){
        float w = wo2[k*Hc + c];
        #pragma unroll
        for(int p = 0; p < 8; p++) acc[p] += op1[(ty*8+p)*Hc + k] * w;
    }
    #pragma unroll
    for(int p = 0; p < 8; p++){
        int r = ty*8 + p;
        xs[r*Hc + c] = hs[r*Hc + c] + acc[p];
    }
    __syncthreads();

    // LayerNorm per row
    {
        int row = tid >> 4, l16 = tid & 15;
        float s = 0.f, s2 = 0.f;
        #pragma unroll
        for(int q = 0; q < 8; q++){
            float v = xs[row*Hc + l16 + q*16];
            s += v; s2 += v*v;
        }
        #pragma unroll
        for(int m = 8; m > 0; m >>= 1){
            s  += __shfl_xor_sync(0xffffffffu, s, m);
            s2 += __shfl_xor_sync(0xffffffffu, s2, m);
        }
        if(l16 == 0){
            float m_ = s * (1.f/128.f);
            mu[row] = m_;
            rsd[row] = rsqrtf(s2 * (1.f/128.f) - m_*m_ + 1e-5f);
        }
    }
    __syncthreads();
    const float* lg = lng + l*Hc;
    const float* lb = lnb + l*Hc;
    #pragma unroll
    for(int p = 0; p < 8; p++){
        int r = ty*8 + p;
        float x = xs[r*Hc + c];
        float hn = ((x - mu[r]) * rsd[r] * lg[c] + lb[c]) * vmsh[r];
        g_h[(size_t)(row0+r)*Hc + c] = hn;
        hs[r*Hc + c] = hn;
    }

    if(has_next){
        __syncthreads();
        int ln = l + 1;
        const float* was = Wa1 + ln*3*Hc*Hc;
        const float* wad = was + Hc*Hc;
        const float* wms = Wm1 + ln*2*Hc*Hc;
        float aa[8], dd[8], mm[8];
        #pragma unroll
        for(int p = 0; p < 8; p++){ aa[p]=0.f; dd[p]=0.f; mm[p]=0.f; }
        #pragma unroll 4
        for(int k = 0; k < Hc; k++){
            float w1 = was[k*Hc + c], w2 = wad[k*Hc + c], w3 = wms[k*Hc + c];
            #pragma unroll
            for(int p = 0; p < 8; p++){
                float h = hs[(ty*8+p)*Hc + k];
                aa[p] += h*w1; dd[p] += h*w2; mm[p] += h*w3;
            }
        }
        #pragma unroll
        for(int p = 0; p < 8; p++){
            size_t r = (size_t)(row0 + ty*8 + p)*Hc + c;
            g_sa[r] = aa[p]; g_da[r] = dd[p]; g_sm[r] = mm[p];
        }
    }
}

// ---------------- decoder (+ fused h copy) ----------------
__global__ void k_dec2(const float* __restrict__ hist, const float* __restrict__ mask,
                       const float* __restrict__ hg, const float* __restrict__ hb,
                       const float* __restrict__ Wh1, const float* __restrict__ bh1,
                       const float* __restrict__ Wh2, const float* __restrict__ bh2,
                       float* __restrict__ out){
    if(blockIdx.x >= 16){
        int i = (blockIdx.x - 16)*128 + threadIdx.x;
        out[384 + i] = g_h[i];
        return;
    }
    int b = blockIdx.x; int t = threadIdx.x;
    __shared__ float x[136], xn[136], hid[Hc];
    __shared__ float red2[4];
    float mv = mask[b*Lc + t];
    float s = mv;
    #pragma unroll
    for(int sft = 16; sft > 0; sft >>= 1) s += __shfl_xor_sync(0xffffffffu, s, sft);
    if((t & 31) == 0) red2[t >> 5] = s;
    __syncthreads();
    float tot = red2[0]+red2[1]+red2[2]+red2[3];
    int vc = (int)tot;
    vc = min(max(vc, 1), Lc);
    int last = vc - 1;

    if(t < Dc) x[t] = hist[((size_t)b*Lc + last)*Dc + t];
    x[Dc + t] = g_h[((size_t)b*Lc + last)*Hc + t];
    __syncthreads();
    float s1 = x[t] + ((t < 8) ? x[128 + t] : 0.f);
    #pragma unroll
    for(int sft = 16; sft > 0; sft >>= 1) s1 += __shfl_xor_sync(0xffffffffu, s1, sft);
    __syncthreads();
    if((t & 31) == 0) red2[t >> 5] = s1;
    __syncthreads();
    float mu = (red2[0]+red2[1]+red2[2]+red2[3]) * (1.f/136.f);
    float d0 = x[t] - mu;
    float s2 = d0*d0;
    if(t < 8){ float d1 = x[128 + t] - mu; s2 += d1*d1; }
    #pragma unroll
    for(int sft = 16; sft > 0; sft >>= 1) s2 += __shfl_xor_sync(0xffffffffu, s2, sft);
    __syncthreads();
    if((t & 31) == 0) red2[t >> 5] = s2;
    __syncthreads();
    float rs = rsqrtf((red2[0]+red2[1]+red2[2]+red2[3]) * (1.f/136.f) + 1e-5f);
    xn[t] = (x[t] - mu) * rs * hg[t] + hb[t];
    if(t < 8) xn[128 + t] = (x[128 + t] - mu) * rs * hg[128 + t] + hb[128 + t];
    __syncthreads();
    float h_ = bh1[t];
    for(int k = 0; k < 136; k++) h_ += xn[k]*Wh1[k*Hc + t];
    hid[t] = fmaxf(h_, 0.f);
    __syncthreads();
    if(t < 24){
        float p = bh2[t];
        for(int k = 0; k < Hc; k++) p += hid[k]*Wh2[k*24 + t];
        if(isnan(p)) p = 0.f;
        else if(isinf(p)) p = (p > 0.f) ? 1e4f : -1e4f;
        out[b*24 + t] = p;
    }
}

// ---------------- launch ----------------
extern "C" void kernel_launch(void* const* d_in, const int* in_sizes, int n_in,
                              void* d_out, int out_size){
    const float* hist = (const float*)d_in[0];
    const float* mask = (const float*)d_in[1];
    const float* Wp   = (const float*)d_in[2];
    const float* bp   = (const float*)d_in[3];
    const float* We1  = (const float*)d_in[4];
    const float* be1  = (const float*)d_in[5];
    const float* We2  = (const float*)d_in[6];
    const float* be2  = (const float*)d_in[7];
    const float* Wa1  = (const float*)d_in[8];
    const float* ba1  = (const float*)d_in[9];
    const float* wa2  = (const float*)d_in[10];
    const float* ba2  = (const float*)d_in[11];
    const float* Wm1  = (const float*)d_in[12];
    const float* bm1  = (const float*)d_in[13];
    const float* Wm2  = (const float*)d_in[14];
    const float* bm2  = (const float*)d_in[15];
    const float* Wo1  = (const float*)d_in[16];
    const float* bo1  = (const float*)d_in[17];
    const float* Wo2  = (const float*)d_in[18];
    const float* bo2  = (const float*)d_in[19];
    const float* lng  = (const float*)d_in[20];
    const float* lnb  = (const float*)d_in[21];
    const float* hg   = (const float*)d_in[22];
    const float* hbv  = (const float*)d_in[23];
    const float* Wh1  = (const float*)d_in[24];
    const float* bh1  = (const float*)d_in[25];
    const float* Wh2  = (const float*)d_in[26];
    const float* bh2  = (const float*)d_in[27];
    float* out = (float*)d_out;

    cudaFuncSetAttribute(k_main11, cudaFuncAttributeMaxDynamicSharedMemorySize, 3*TILE_BYTES);

    k_ts2<<<Bc, 128>>>(hist);
    k_prepwb<<<NLc*129, Hc>>>(We2, be2, Wa1, Wm1, ba1, bm1, Wm2, bm2, Wo1, bo1);
    k_h0s<<<Bc*Lc/16, 256>>>(hist, mask, Wp, bp, Wa1, Wm1);
    for(int l = 0; l < NLc; l++){
        k_main11<<<Bc*Lc, 512, 3*TILE_BYTES>>>(l, hist, mask, We1, be1, wa2, ba2);
        k_post4<<<Bc*Lc/16, 256>>>(l, (l+1 < NLc) ? 1 : 0, mask,
                                   Wo1, Wo2, bo2, lng, lnb, Wa1, Wm1);
    }
    int do_copy = (out_size >= 384 + Bc*Lc*Hc) ? 1 : 0;
    k_dec2<<<16 + (do_copy ? (Bc*Lc*Hc)/128 : 0), 128>>>(hist, mask, hg, hbv, Wh1, bh1, Wh2, bh2, out);
}

// round 16
// speedup vs baseline: 1.1267x; 1.0236x over previous
#include <cuda_runtime.h>
#include <cuda_bf16.h>
#include <math.h>
#include <stdint.h>

#define Bc 16
#define Lc 128
#define Dc 8
#define Hc 128
#define NLc 2

// bf16 tile geometry: [128 rows][136 cols] bf16, pitch 272B
#define WPITCH 136
#define TILE_ELEMS (128*WPITCH)          // 17408
#define TILE_BYTES (TILE_ELEMS*2)        // 34816

// ---------------- scratch (static device globals; no allocation) ----------------
__device__ __align__(16) float g_ts[Bc*Lc];
__device__ __align__(16) float g_h[Bc*Lc*Hc];
__device__ __align__(16) float g_sa[Bc*Lc*Hc];
__device__ __align__(16) float g_da[Bc*Lc*Hc];
__device__ __align__(16) float g_sm[Bc*Lc*Hc];
__device__ __align__(16) float g_aggpre[Bc*Lc*Hc];
__device__ __align__(16) float g_ba[NLc*Hc];
__device__ __align__(16) float g_bm[NLc*Hc];
__device__ __align__(16) float g_Wco[NLc*Hc*Hc];   // Wm2 @ Wo1a folded
__device__ __align__(16) float g_bco[NLc*Hc];      // bm2 @ Wo1a + bo1
// folded weights as bf16, [k][c] rows padded to 136: per layer Wa | Wm
__device__ __align__(16) __nv_bfloat16 g_Wbf[NLc*2*TILE_ELEMS];

// ---------------- helpers ----------------
__device__ __forceinline__ uint32_t smem_u32(const void* p){
    uint32_t a;
    asm("{ .reg .u64 t; cvta.to.shared.u64 t, %1; cvt.u32.u64 %0, t; }" : "=r"(a) : "l"(p));
    return a;
}
__device__ __forceinline__ void cp16(void* dst_smem, const void* src){
    unsigned sdst = (unsigned)__cvta_generic_to_shared(dst_smem);
    asm volatile("cp.async.cg.shared.global [%0], [%1], 16;" :: "r"(sdst), "l"(src));
}
__device__ __forceinline__ float tanh_fast(float x){
    float r; asm("tanh.approx.f32 %0, %1;" : "=f"(r) : "f"(x)); return r;
}
__device__ __forceinline__ void ldsm4(uint32_t &r0,uint32_t &r1,uint32_t &r2,uint32_t &r3,uint32_t a){
    asm volatile("ldmatrix.sync.aligned.m8n8.x4.shared.b16 {%0,%1,%2,%3},[%4];"
        : "=r"(r0),"=r"(r1),"=r"(r2),"=r"(r3) : "r"(a));
}
__device__ __forceinline__ void ldsm4t(uint32_t &r0,uint32_t &r1,uint32_t &r2,uint32_t &r3,uint32_t a){
    asm volatile("ldmatrix.sync.aligned.m8n8.x4.trans.shared.b16 {%0,%1,%2,%3},[%4];"
        : "=r"(r0),"=r"(r1),"=r"(r2),"=r"(r3) : "r"(a));
}
__device__ __forceinline__ void mma16816(float* d, uint32_t a0,uint32_t a1,uint32_t a2,uint32_t a3,
                                         uint32_t b0,uint32_t b1){
    asm volatile("mma.sync.aligned.m16n8k16.row.col.f32.bf16.bf16.f32 "
        "{%0,%1,%2,%3},{%4,%5,%6,%7},{%8,%9},{%0,%1,%2,%3};"
        : "+f"(d[0]),"+f"(d[1]),"+f"(d[2]),"+f"(d[3])
        : "r"(a0),"r"(a1),"r"(a2),"r"(a3),"r"(b0),"r"(b1));
}
// pack two floats to bf16x2 (v0 -> low half, v1 -> high)
__device__ __forceinline__ uint32_t packbf2(float v0, float v1){
    uint32_t r; asm("cvt.rn.bf16x2.f32 %0, %1, %2;" : "=r"(r) : "f"(v1), "f"(v0)); return r;
}

// ---------------- fused prologue: ts scan | weight folds | h0+sadam ----------------
// grid: [0,16) ts scan; [16, 16+258) prepwb; [16+258, 16+258+128) h0s. 256 threads.
__global__ __launch_bounds__(256)
void k_pre(const float* __restrict__ hist, const float* __restrict__ mask,
           const float* __restrict__ Wp, const float* __restrict__ bp,
           const float* __restrict__ We2, const float* __restrict__ be2,
           const float* __restrict__ Wa1, const float* __restrict__ Wm1,
           const float* __restrict__ ba1, const float* __restrict__ bm1,
           const float* __restrict__ Wm2, const float* __restrict__ bm2,
           const float* __restrict__ Wo1, const float* __restrict__ bo1){
    int blk = blockIdx.x;
    int tid = threadIdx.x;
    if(blk < 16){
        // ---- ts cumsum (first 128 threads) ----
        if(tid >= 128) return;
        int b = blk;
        int lane = tid & 31, w = tid >> 5;
        __shared__ float wsum[4];
        float v = fmaxf(hist[(b*Lc + tid)*Dc + 5], 0.f);
        float s = v;
        #pragma unroll
        for(int d = 1; d < 32; d <<= 1){
            float o = __shfl_up_sync(0xffffffffu, s, d);
            if(lane >= d) s += o;
        }
        if(lane == 31) wsum[w] = s;
        __syncwarp();
        asm volatile("bar.sync 1, 128;" ::: "memory");
        float pre = 0.f;
        #pragma unroll
        for(int q = 0; q < 4; q++) pre += (q < w) ? wsum[q] : 0.f;
        g_ts[b*Lc + tid] = s + pre;
        return;
    }
    if(blk < 16 + NLc*129){
        // ---- weight folds (first 128 threads) ----
        if(tid >= 128) return;
        int bb = blk - 16;
        int l = bb / 129, kk = bb % 129;
        int c = tid;
        __shared__ float ws[Hc], ws2[Hc];
        if(kk < Hc){
            ws[c]  = We2[l*Hc*Hc + kk*Hc + c];
            ws2[c] = Wm2[l*Hc*Hc + kk*Hc + c];
        } else {
            ws[c]  = be2[l*Hc + c];
            ws2[c] = bm2[l*Hc + c];
        }
        asm volatile("bar.sync 1, 128;" ::: "memory");
        const float* wa  = Wa1 + l*3*Hc*Hc + 2*Hc*Hc;
        const float* wm  = Wm1 + l*2*Hc*Hc + Hc*Hc;
        const float* wo1a = Wo1 + l*2*Hc*Hc + Hc*Hc;
        float sa = 0.f, sm = 0.f, sco = 0.f;
        #pragma unroll 4
        for(int r = 0; r < Hc; r++){
            float w = ws[r], w2 = ws2[r];
            sa += w*wa[r*Hc + c]; sm += w*wm[r*Hc + c]; sco += w2*wo1a[r*Hc + c];
        }
        if(kk < Hc){
            __nv_bfloat16* base = g_Wbf + (size_t)l*2*TILE_ELEMS;
            base[             kk*WPITCH + c] = __float2bfloat16(sa);
            base[TILE_ELEMS + kk*WPITCH + c] = __float2bfloat16(sm);
            g_Wco[(l*Hc + kk)*Hc + c] = sco;
        } else {
            g_ba[l*Hc + c] = sa + ba1[l*Hc + c];
            g_bm[l*Hc + c] = sm + bm1[l*Hc + c];
            g_bco[l*Hc + c] = sco + bo1[l*Hc + c];
        }
        return;
    }
    // ---- h0 + sadam for layer 0 (256 threads, 16 rows) ----
    {
        int row0 = (blk - 16 - NLc*129) * 16;
        int c = tid & 127, ty = tid >> 7;
        __shared__ float xs[16*Dc], hs[16*Hc], vmsh[16];
        if(tid < 128) xs[tid] = hist[(size_t)row0*Dc + tid];
        if(tid < 16)  vmsh[tid] = mask[row0 + tid] > 0.f ? 1.f : 0.f;
        __syncthreads();
        float acc[8];
        #pragma unroll
        for(int p = 0; p < 8; p++) acc[p] = bp[c];
        #pragma unroll
        for(int d = 0; d < Dc; d++){
            float w = Wp[d*Hc + c];
            #pragma unroll
            for(int p = 0; p < 8; p++) acc[p] += xs[(ty*8+p)*Dc + d] * w;
        }
        #pragma unroll
        for(int p = 0; p < 8; p++){
            int r = ty*8 + p;
            float h = acc[p] * vmsh[r];
            hs[r*Hc + c] = h;
            g_h[(size_t)(row0+r)*Hc + c] = h;
        }
        __syncthreads();
        const float* was = Wa1;
        const float* wad = was + Hc*Hc;
        const float* wms = Wm1;
        float aa[8], dd[8], mm[8];
        #pragma unroll
        for(int p = 0; p < 8; p++){ aa[p]=0.f; dd[p]=0.f; mm[p]=0.f; }
        #pragma unroll 4
        for(int k = 0; k < Hc; k++){
            float w1 = was[k*Hc + c], w2 = wad[k*Hc + c], w3 = wms[k*Hc + c];
            #pragma unroll
            for(int p = 0; p < 8; p++){
                float h = hs[(ty*8+p)*Hc + k];
                aa[p] += h*w1; dd[p] += h*w2; mm[p] += h*w3;
            }
        }
        #pragma unroll
        for(int p = 0; p < 8; p++){
            size_t r = (size_t)(row0 + ty*8 + p)*Hc + c;
            g_sa[r] = aa[p]; g_da[r] = dd[p]; g_sm[r] = mm[p];
        }
    }
}

// ---------------- main fused kernel (UNCHANGED — proven best) ----------------
extern __shared__ char dsmc[];

__global__ __launch_bounds__(512, 2)
void k_main11(int l, const float* __restrict__ hist, const float* __restrict__ mask,
              const float* __restrict__ We1, const float* __restrict__ be1,
              const float* __restrict__ wa2, const float* __restrict__ ba2){
    __shared__ float we1s[4*Hc], be1s[Hc], sab[Hc], smb[Hc], wa2s[Hc];
    __shared__ float attp[4][Lc], wsoft[Lc], red[8], redp[4][Hc];

    int bi = blockIdx.x;
    int b = bi >> 7, i = bi & 127;
    int tid = threadIdx.x;
    int wid = tid >> 5, lane = tid & 31;
    int j = tid & 127;

    {
        const char* wsrc = (const char*)(g_Wbf + (size_t)l*2*TILE_ELEMS);
        char* wdst = dsmc + TILE_BYTES;
        #pragma unroll
        for(int q = 0; q < 8; q++){
            int off = (q*512 + tid)*16;
            cp16(wdst + off, wsrc + off);
        }
        if(tid < 256) cp16(wdst + (4096 + tid)*16, wsrc + (4096 + tid)*16);
        asm volatile("cp.async.commit_group;" ::: "memory");
    }

    if(tid < 128){
        #pragma unroll
        for(int q = 0; q < 4; q++) we1s[q*Hc + tid] = We1[l*4*Hc + q*Hc + tid];
        be1s[tid] = be1[l*Hc + tid];
        sab[tid]  = g_sa[(size_t)bi*Hc + tid] + g_ba[l*Hc + tid];
        smb[tid]  = g_sm[(size_t)bi*Hc + tid] + g_bm[l*Hc + tid];
        wa2s[tid] = wa2[l*Hc + tid];
    }

    const float* hb_ = hist + (size_t)b*Lc*Dc;
    float vldj, vi;
    {
        float lat_i = hb_[i*Dc + 0], lon_i = hb_[i*Dc + 1], src_i = hb_[i*Dc + 6];
        float ts_i = g_ts[b*Lc + i];
        float latj = hb_[j*Dc + 0], lonj = hb_[j*Dc + 1], srcj = hb_[j*Dc + 6];
        float tsj = g_ts[b*Lc + j];
        float dl = lat_i - latj, dn = lon_i - lonj;
        float dist = sqrtf(dl*dl + dn*dn + 1e-8f);
        float dtv = fabsf(ts_i - tsj) * (1.f/300.f);
        float ssv = (src_i == srcj) ? 1.f : 0.f;
        float diag = (j == i) ? 1.f : 0.f;
        vldj = (mask[b*Lc + j] > 0.f) ? 1.f : 0.f;
        vi   = (mask[b*Lc + i] > 0.f) ? 1.f : 0.f;
        __syncthreads();

        int q = tid >> 7;
        char* Th = dsmc + (size_t)j*272;
        #pragma unroll
        for(int kk = 0; kk < 16; kk++){
            int k = q*32 + kk*2;
            float v0 = fmaxf(dist*we1s[k]   + dtv*we1s[Hc+k]   + ssv*we1s[2*Hc+k]   + diag*we1s[3*Hc+k]   + be1s[k],   0.f);
            float v1 = fmaxf(dist*we1s[k+1] + dtv*we1s[Hc+k+1] + ssv*we1s[2*Hc+k+1] + diag*we1s[3*Hc+k+1] + be1s[k+1], 0.f);
            *(uint32_t*)(Th + k*2) = packbf2(v0, v1);
        }
    }
    asm volatile("cp.async.wait_group 0;" ::: "memory");
    __syncthreads();

    int jb = wid & 3, cb = wid >> 2;
    int jt = jb*32, ch = cb*32;
    uint32_t base = smem_u32(dsmc);
    uint32_t aT0 = base + (uint32_t)((jt + (lane & 15))*272 + ((lane >> 4) << 4));
    uint32_t aT1 = aT0 + 16*272;
    uint32_t wBa = base + (uint32_t)(TILE_BYTES   + (lane & 15)*272 + ch*2 + ((lane >> 4) << 4));
    uint32_t wBm = wBa + (uint32_t)TILE_BYTES;
    int gq = lane >> 2, tq = lane & 3;

    float acc[32];

    // PHASE A: attention GEMM
    #pragma unroll
    for(int q = 0; q < 32; q++) acc[q] = 0.f;
    #pragma unroll
    for(int ks = 0; ks < 8; ks++){
        uint32_t a0,a1,a2,a3, c0,c1,c2,c3;
        ldsm4(a0,a1,a2,a3, aT0 + ks*32);
        ldsm4(c0,c1,c2,c3, aT1 + ks*32);
        uint32_t wrow = wBa + ks*4352;
        uint32_t B0,B1,B2,B3, B4,B5,B6,B7;
        ldsm4t(B0,B1,B2,B3, wrow);
        ldsm4t(B4,B5,B6,B7, wrow + 32);
        mma16816(acc+0,  a0,a1,a2,a3, B0,B1);
        mma16816(acc+4,  a0,a1,a2,a3, B2,B3);
        mma16816(acc+8,  a0,a1,a2,a3, B4,B5);
        mma16816(acc+12, a0,a1,a2,a3, B6,B7);
        mma16816(acc+16, c0,c1,c2,c3, B0,B1);
        mma16816(acc+20, c0,c1,c2,c3, B2,B3);
        mma16816(acc+24, c0,c1,c2,c3, B4,B5);
        mma16816(acc+28, c0,c1,c2,c3, B6,B7);
    }
    #pragma unroll
    for(int t16 = 0; t16 < 2; t16++){
        int jA = jt + t16*16 + gq, jB = jA + 8;
        const float* daA = g_da + ((size_t)(b*Lc + jA))*Hc;
        const float* daB = daA + 8*Hc;
        float sA = 0.f, sB = 0.f;
        #pragma unroll
        for(int nq = 0; nq < 4; nq++){
            int c0 = ch + nq*8 + tq*2;
            const float* d = acc + t16*16 + nq*4;
            float2 dA = *(const float2*)(daA + c0);
            float2 dB = *(const float2*)(daB + c0);
            sA += wa2s[c0]  *tanh_fast(sab[c0]  + dA.x + d[0]);
            sA += wa2s[c0+1]*tanh_fast(sab[c0+1]+ dA.y + d[1]);
            sB += wa2s[c0]  *tanh_fast(sab[c0]  + dB.x + d[2]);
            sB += wa2s[c0+1]*tanh_fast(sab[c0+1]+ dB.y + d[3]);
        }
        sA += __shfl_xor_sync(0xffffffffu, sA, 1);
        sA += __shfl_xor_sync(0xffffffffu, sA, 2);
        sB += __shfl_xor_sync(0xffffffffu, sB, 1);
        sB += __shfl_xor_sync(0xffffffffu, sB, 2);
        if(tq == 0){ attp[cb][jA] = sA; attp[cb][jB] = sB; }
    }

    // PHASE B: message GEMM (independent of softmax)
    #pragma unroll
    for(int q = 0; q < 32; q++) acc[q] = 0.f;
    #pragma unroll
    for(int ks = 0; ks < 8; ks++){
        uint32_t a0,a1,a2,a3, c0,c1,c2,c3;
        ldsm4(a0,a1,a2,a3, aT0 + ks*32);
        ldsm4(c0,c1,c2,c3, aT1 + ks*32);
        uint32_t wrow = wBm + ks*4352;
        uint32_t B0,B1,B2,B3, B4,B5,B6,B7;
        ldsm4t(B0,B1,B2,B3, wrow);
        ldsm4t(B4,B5,B6,B7, wrow + 32);
        mma16816(acc+0,  a0,a1,a2,a3, B0,B1);
        mma16816(acc+4,  a0,a1,a2,a3, B2,B3);
        mma16816(acc+8,  a0,a1,a2,a3, B4,B5);
        mma16816(acc+12, a0,a1,a2,a3, B6,B7);
        mma16816(acc+16, c0,c1,c2,c3, B0,B1);
        mma16816(acc+20, c0,c1,c2,c3, B2,B3);
        mma16816(acc+24, c0,c1,c2,c3, B4,B5);
        mma16816(acc+28, c0,c1,c2,c3, B6,B7);
    }
    __syncthreads();

    // softmax over j
    const float inv = 0.088388347648318440550f;
    float sc = -1e9f, e = 0.f;
    if(tid < 128){
        float a = (attp[0][tid] + attp[1][tid] + attp[2][tid] + attp[3][tid] + ba2[l]) * inv;
        bool ok = (vldj > 0.f) && (vi > 0.f);
        sc = ok ? a : -1e9f;
        float m = sc;
        #pragma unroll
        for(int s2 = 16; s2 > 0; s2 >>= 1) m = fmaxf(m, __shfl_xor_sync(0xffffffffu, m, s2));
        if((tid & 31) == 0) red[tid >> 5] = m;
    }
    __syncthreads();
    float bmax = fmaxf(fmaxf(red[0], red[1]), fmaxf(red[2], red[3]));
    if(tid < 128){
        e = expf(sc - bmax);
        float s2 = e;
        #pragma unroll
        for(int m = 16; m > 0; m >>= 1) s2 += __shfl_xor_sync(0xffffffffu, s2, m);
        if((tid & 31) == 0) red[4 + (tid >> 5)] = s2;
    }
    __syncthreads();
    if(tid < 128){
        float tot = red[4]+red[5]+red[6]+red[7];
        wsoft[tid] = e / tot;
    }
    __syncthreads();

    // message epilogue
    float* su = (float*)dsmc;
    {
        float v[8];
        #pragma unroll
        for(int p = 0; p < 8; p++) v[p] = 0.f;
        #pragma unroll
        for(int t16 = 0; t16 < 2; t16++){
            int jA = jt + t16*16 + gq, jB = jA + 8;
            float wA = wsoft[jA], wB2 = wsoft[jB];
            #pragma unroll
            for(int nq = 0; nq < 4; nq++){
                int c0 = ch + nq*8 + tq*2;
                const float* d = acc + t16*16 + nq*4;
                v[nq*2]   += wA*fmaxf(smb[c0]  + d[0], 0.f) + wB2*fmaxf(smb[c0]  + d[2], 0.f);
                v[nq*2+1] += wA*fmaxf(smb[c0+1]+ d[1], 0.f) + wB2*fmaxf(smb[c0+1]+ d[3], 0.f);
            }
        }
        int p = jb*8 + gq;
        #pragma unroll
        for(int nq = 0; nq < 4; nq++){
            int c0 = ch + nq*8 + tq*2;
            *(float2*)(su + p*130 + c0) = make_float2(v[nq*2], v[nq*2+1]);
        }
    }
    __syncthreads();
    {
        int qq = tid >> 7, c = tid & 127;
        float s = 0.f;
        #pragma unroll
        for(int r = 0; r < 8; r++) s += su[(qq*8 + r)*130 + c];
        redp[qq][c] = s;
    }
    __syncthreads();
    if(tid < 128){
        g_aggpre[(size_t)bi*Hc + tid] = redp[0][tid] + redp[1][tid] + redp[2][tid] + redp[3][tid];
    }
}

// ---------------- epilogue per 16 rows: 512 threads, 4 rows/thread ----------------
__global__ __launch_bounds__(512)
void k_post5(int l, int has_next, const float* __restrict__ mask,
             const float* __restrict__ Wo1,
             const float* __restrict__ Wo2, const float* __restrict__ bo2,
             const float* __restrict__ lng, const float* __restrict__ lnb,
             const float* __restrict__ Wa1, const float* __restrict__ Wm1){
    int row0 = blockIdx.x * 16;
    int tid = threadIdx.x;
    int c = tid & 127, ty = tid >> 7;   // ty 0..3, 4 rows each
    __shared__ float hs[16*Hc], as_[16*Hc], op1[16*Hc], xs[16*Hc];
    __shared__ float mu[16], rsd[16], vmsh[16];

    #pragma unroll
    for(int q = 0; q < 4; q++){
        int idx = q*512 + tid;
        hs[idx]  = g_h[(size_t)row0*Hc + idx];
        as_[idx] = g_aggpre[(size_t)row0*Hc + idx];
    }
    if(tid < 16) vmsh[tid] = mask[row0 + tid] > 0.f ? 1.f : 0.f;
    __syncthreads();

    float acc[4];
    // stage 1: op1 = relu(h @ Wo1h + aggpre @ Wco + bco)
    const float* wo1h = Wo1 + l*2*Hc*Hc;
    const float* wco  = g_Wco + l*Hc*Hc;
    #pragma unroll
    for(int p = 0; p < 4; p++) acc[p] = g_bco[l*Hc + c];
    #pragma unroll 4
    for(int k = 0; k < Hc; k++){
        float w1 = wo1h[k*Hc + c], w2 = wco[k*Hc + c];
        #pragma unroll
        for(int p = 0; p < 4; p++)
            acc[p] += hs[(ty*4+p)*Hc + k]*w1 + as_[(ty*4+p)*Hc + k]*w2;
    }
    #pragma unroll
    for(int p = 0; p < 4; p++) op1[(ty*4+p)*Hc + c] = fmaxf(acc[p], 0.f);
    __syncthreads();

    // stage 2: x = h + op1 @ Wo2 + bo2
    const float* wo2 = Wo2 + l*Hc*Hc;
    #pragma unroll
    for(int p = 0; p < 4; p++) acc[p] = bo2[l*Hc + c];
    #pragma unroll 4
    for(int k = 0; k < Hc; k++){
        float w = wo2[k*Hc + c];
        #pragma unroll
        for(int p = 0; p < 4; p++) acc[p] += op1[(ty*4+p)*Hc + k] * w;
    }
    #pragma unroll
    for(int p = 0; p < 4; p++){
        int r = ty*4 + p;
        xs[r*Hc + c] = hs[r*Hc + c] + acc[p];
    }
    __syncthreads();

    // LayerNorm per row (first 256 threads)
    if(tid < 256){
        int row = tid >> 4, l16 = tid & 15;
        float s = 0.f, s2 = 0.f;
        #pragma unroll
        for(int q = 0; q < 8; q++){
            float v = xs[row*Hc + l16 + q*16];
            s += v; s2 += v*v;
        }
        #pragma unroll
        for(int m = 8; m > 0; m >>= 1){
            s  += __shfl_xor_sync(0xffffffffu, s, m);
            s2 += __shfl_xor_sync(0xffffffffu, s2, m);
        }
        if(l16 == 0){
            float m_ = s * (1.f/128.f);
            mu[row] = m_;
            rsd[row] = rsqrtf(s2 * (1.f/128.f) - m_*m_ + 1e-5f);
        }
    }
    __syncthreads();
    const float* lg = lng + l*Hc;
    const float* lb = lnb + l*Hc;
    #pragma unroll
    for(int p = 0; p < 4; p++){
        int r = ty*4 + p;
        float x = xs[r*Hc + c];
        float hn = ((x - mu[r]) * rsd[r] * lg[c] + lb[c]) * vmsh[r];
        g_h[(size_t)(row0+r)*Hc + c] = hn;
        hs[r*Hc + c] = hn;
    }

    if(has_next){
        __syncthreads();
        int ln = l + 1;
        const float* was = Wa1 + ln*3*Hc*Hc;
        const float* wad = was + Hc*Hc;
        const float* wms = Wm1 + ln*2*Hc*Hc;
        float aa[4], dd[4], mm[4];
        #pragma unroll
        for(int p = 0; p < 4; p++){ aa[p]=0.f; dd[p]=0.f; mm[p]=0.f; }
        #pragma unroll 4
        for(int k = 0; k < Hc; k++){
            float w1 = was[k*Hc + c], w2 = wad[k*Hc + c], w3 = wms[k*Hc + c];
            #pragma unroll
            for(int p = 0; p < 4; p++){
                float h = hs[(ty*4+p)*Hc + k];
                aa[p] += h*w1; dd[p] += h*w2; mm[p] += h*w3;
            }
        }
        #pragma unroll
        for(int p = 0; p < 4; p++){
            size_t r = (size_t)(row0 + ty*4 + p)*Hc + c;
            g_sa[r] = aa[p]; g_da[r] = dd[p]; g_sm[r] = mm[p];
        }
    }
}

// ---------------- decoder (+ fused h copy) ----------------
__global__ void k_dec2(const float* __restrict__ hist, const float* __restrict__ mask,
                       const float* __restrict__ hg, const float* __restrict__ hb,
                       const float* __restrict__ Wh1, const float* __restrict__ bh1,
                       const float* __restrict__ Wh2, const float* __restrict__ bh2,
                       float* __restrict__ out){
    if(blockIdx.x >= 16){
        int i = (blockIdx.x - 16)*128 + threadIdx.x;
        out[384 + i] = g_h[i];
        return;
    }
    int b = blockIdx.x; int t = threadIdx.x;
    __shared__ float x[136], xn[136], hid[Hc];
    __shared__ float red2[4];
    float mv = mask[b*Lc + t];
    float s = mv;
    #pragma unroll
    for(int sft = 16; sft > 0; sft >>= 1) s += __shfl_xor_sync(0xffffffffu, s, sft);
    if((t & 31) == 0) red2[t >> 5] = s;
    __syncthreads();
    float tot = red2[0]+red2[1]+red2[2]+red2[3];
    int vc = (int)tot;
    vc = min(max(vc, 1), Lc);
    int last = vc - 1;

    if(t < Dc) x[t] = hist[((size_t)b*Lc + last)*Dc + t];
    x[Dc + t] = g_h[((size_t)b*Lc + last)*Hc + t];
    __syncthreads();
    float s1 = x[t] + ((t < 8) ? x[128 + t] : 0.f);
    #pragma unroll
    for(int sft = 16; sft > 0; sft >>= 1) s1 += __shfl_xor_sync(0xffffffffu, s1, sft);
    __syncthreads();
    if((t & 31) == 0) red2[t >> 5] = s1;
    __syncthreads();
    float mu = (red2[0]+red2[1]+red2[2]+red2[3]) * (1.f/136.f);
    float d0 = x[t] - mu;
    float s2 = d0*d0;
    if(t < 8){ float d1 = x[128 + t] - mu; s2 += d1*d1; }
    #pragma unroll
    for(int sft = 16; sft > 0; sft >>= 1) s2 += __shfl_xor_sync(0xffffffffu, s2, sft);
    __syncthreads();
    if((t & 31) == 0) red2[t >> 5] = s2;
    __syncthreads();
    float rs = rsqrtf((red2[0]+red2[1]+red2[2]+red2[3]) * (1.f/136.f) + 1e-5f);
    xn[t] = (x[t] - mu) * rs * hg[t] + hb[t];
    if(t < 8) xn[128 + t] = (x[128 + t] - mu) * rs * hg[128 + t] + hb[128 + t];
    __syncthreads();
    float h_ = bh1[t];
    for(int k = 0; k < 136; k++) h_ += xn[k]*Wh1[k*Hc + t];
    hid[t] = fmaxf(h_, 0.f);
    __syncthreads();
    if(t < 24){
        float p = bh2[t];
        for(int k = 0; k < Hc; k++) p += hid[k]*Wh2[k*24 + t];
        if(isnan(p)) p = 0.f;
        else if(isinf(p)) p = (p > 0.f) ? 1e4f : -1e4f;
        out[b*24 + t] = p;
    }
}

// ---------------- launch ----------------
extern "C" void kernel_launch(void* const* d_in, const int* in_sizes, int n_in,
                              void* d_out, int out_size){
    const float* hist = (const float*)d_in[0];
    const float* mask = (const float*)d_in[1];
    const float* Wp   = (const float*)d_in[2];
    const float* bp   = (const float*)d_in[3];
    const float* We1  = (const float*)d_in[4];
    const float* be1  = (const float*)d_in[5];
    const float* We2  = (const float*)d_in[6];
    const float* be2  = (const float*)d_in[7];
    const float* Wa1  = (const float*)d_in[8];
    const float* ba1  = (const float*)d_in[9];
    const float* wa2  = (const float*)d_in[10];
    const float* ba2  = (const float*)d_in[11];
    const float* Wm1  = (const float*)d_in[12];
    const float* bm1  = (const float*)d_in[13];
    const float* Wm2  = (const float*)d_in[14];
    const float* bm2  = (const float*)d_in[15];
    const float* Wo1  = (const float*)d_in[16];
    const float* bo1  = (const float*)d_in[17];
    const float* Wo2  = (const float*)d_in[18];
    const float* bo2  = (const float*)d_in[19];
    const float* lng  = (const float*)d_in[20];
    const float* lnb  = (const float*)d_in[21];
    const float* hg   = (const float*)d_in[22];
    const float* hbv  = (const float*)d_in[23];
    const float* Wh1  = (const float*)d_in[24];
    const float* bh1  = (const float*)d_in[25];
    const float* Wh2  = (const float*)d_in[26];
    const float* bh2  = (const float*)d_in[27];
    float* out = (float*)d_out;

    cudaFuncSetAttribute(k_main11, cudaFuncAttributeMaxDynamicSharedMemorySize, 3*TILE_BYTES);

    k_pre<<<16 + NLc*129 + Bc*Lc/16, 256>>>(hist, mask, Wp, bp, We2, be2,
                                            Wa1, Wm1, ba1, bm1, Wm2, bm2, Wo1, bo1);
    for(int l = 0; l < NLc; l++){
        k_main11<<<Bc*Lc, 512, 3*TILE_BYTES>>>(l, hist, mask, We1, be1, wa2, ba2);
        k_post5<<<Bc*Lc/16, 512>>>(l, (l+1 < NLc) ? 1 : 0, mask,
                                   Wo1, Wo2, bo2, lng, lnb, Wa1, Wm1);
    }
    int do_copy = (out_size >= 384 + Bc*Lc*Hc) ? 1 : 0;
    k_dec2<<<16 + (do_copy ? (Bc*Lc*Hc)/128 : 0), 128>>>(hist, mask, hg, hbv, Wh1, bh1, Wh2, bh2, out);
}